// round 16
// baseline (speedup 1.0000x reference)
#include <cuda_runtime.h>
#include <cuda_bf16.h>
#include <cstdint>

// ---------------------------------------------------------------------------
// Problem constants
// ---------------------------------------------------------------------------
constexpr int B     = 8;
constexpr int L     = 256;
constexpr int D     = 768;
constexpr int H     = 12;
constexpr int DH    = 64;          // D / H
constexpr int M     = B * L;       // 2048 total query rows
constexpr int NDICT = 16384;
constexpr int KP    = 8;           // final top-k
constexpr int KC    = 16;          // candidate count from approx sim
constexpr int SKG   = L * KP;      // 2048 kv rows per batch (cross-attn)
constexpr int BH    = B * H;       // 96

// ---------------------------------------------------------------------------
// Device-global scratch (no dynamic allocation allowed)
// ---------------------------------------------------------------------------
__device__ __align__(16) float g_gnorm[(size_t)NDICT * D];
__device__ __align__(16) __nv_bfloat16 g_gnorm_bf[(size_t)NDICT * D];
__device__ __align__(16) __nv_bfloat16 g_local_bf[(size_t)M * D];
__device__ __align__(16) float g_sim[(size_t)M * NDICT];
__device__ int   g_cand[(size_t)M * KC];
__device__ int   g_topk[(size_t)M * KP];
__device__ __align__(16) float g_gfeats[(size_t)B * SKG * D];
__device__ __align__(16) float g_q[(size_t)M * D];
__device__ __align__(16) float g_q2[(size_t)M * D];
__device__ __align__(16) float g_k[(size_t)B * SKG * D];
__device__ __align__(16) float g_v[(size_t)B * SKG * D];
__device__ __align__(16) float g_ctx[(size_t)M * D];
__device__ __align__(16) float g_ctx2[(size_t)M * D];
__device__ __align__(16) float g_proj[(size_t)M * D];
__device__ __align__(16) float g_proj2[(size_t)M * D];

#define DEV_INLINE __device__ __forceinline__

DEV_INLINE float blockReduceSum(float v, float* sh) {
    int tid = threadIdx.x;
    sh[tid] = v; __syncthreads();
    #pragma unroll
    for (int s = 128; s > 0; s >>= 1) {
        if (tid < s) sh[tid] += sh[tid + s];
        __syncthreads();
    }
    float r = sh[0]; __syncthreads();
    return r;
}

// jax.lax.top_k order: value desc, ties -> lower index first.
DEV_INLINE bool tk_better(float v, int i, float tv, int ti) {
    return (v > tv) || (v == tv && i < ti);
}

// Packed candidate key: top-18 bits = sortable float, low-14 = idx ^ 0x3FFF.
// Larger key == better (value desc, value-ties -> lower index).
DEV_INLINE uint32_t pack_key(float v, int idx) {
    uint32_t b = __float_as_uint(v);
    b ^= (b & 0x80000000u) ? 0xFFFFFFFFu : 0x80000000u;
    return (b & 0xFFFFC000u) | (uint32_t)((idx ^ 0x3FFF) & 0x3FFF);
}
DEV_INLINE int unpack_idx(uint32_t k) { return (int)((k & 0x3FFFu) ^ 0x3FFFu); }

DEV_INLINE void kswap(uint32_t& a, uint32_t& b) {  // ensure a >= b
    uint32_t hi = umax(a, b), lo = umin(a, b);
    a = hi; b = lo;
}

// ---------------------------------------------------------------------------
// mma + cp.async helpers
// ---------------------------------------------------------------------------
DEV_INLINE void mma_tf32(float& c0, float& c1, float& c2, float& c3,
                         uint32_t a0, uint32_t a1, uint32_t a2, uint32_t a3,
                         uint32_t b0, uint32_t b1) {
    asm volatile(
        "mma.sync.aligned.m16n8k8.row.col.f32.tf32.tf32.f32 "
        "{%0,%1,%2,%3}, {%4,%5,%6,%7}, {%8,%9}, {%0,%1,%2,%3};"
        : "+f"(c0), "+f"(c1), "+f"(c2), "+f"(c3)
        : "r"(a0), "r"(a1), "r"(a2), "r"(a3), "r"(b0), "r"(b1));
}

DEV_INLINE void mma_bf16(float& c0, float& c1, float& c2, float& c3,
                         uint32_t a0, uint32_t a1, uint32_t a2, uint32_t a3,
                         uint32_t b0, uint32_t b1) {
    asm volatile(
        "mma.sync.aligned.m16n8k16.row.col.f32.bf16.bf16.f32 "
        "{%0,%1,%2,%3}, {%4,%5,%6,%7}, {%8,%9}, {%0,%1,%2,%3};"
        : "+f"(c0), "+f"(c1), "+f"(c2), "+f"(c3)
        : "r"(a0), "r"(a1), "r"(a2), "r"(a3), "r"(b0), "r"(b1));
}

DEV_INLINE void cpasync16(uint32_t dst_smem_bytes, const void* src) {
    asm volatile("cp.async.cg.shared.global [%0], [%1], 16;\n"
                 :: "r"(dst_smem_bytes), "l"(src));
}
DEV_INLINE void cp_commit() { asm volatile("cp.async.commit_group;\n" ::); }
DEV_INLINE void cp_wait1()  { asm volatile("cp.async.wait_group 1;\n" ::); }
DEV_INLINE void cp_wait0()  { asm volatile("cp.async.wait_group 0;\n" ::); }

// ---------------------------------------------------------------------------
// bf16 NT GEMM for the approximate sim matrix.
// ---------------------------------------------------------------------------
__global__ __launch_bounds__(256) void bf16gemm_nt(
    const __nv_bfloat16* __restrict__ Ag, const __nv_bfloat16* __restrict__ Bg,
    float* __restrict__ Cg, int Kdim, int lda, int ldb, int ldc) {
    constexpr int BK = 32;
    constexpr int RSTR = 20;                 // u32 per row (80 bytes)
    constexpr int ASZ = 128 * RSTR;          // 2560 u32
    constexpr int STG = 2 * ASZ;             // A + B

    extern __shared__ uint32_t dynsmem[];
    uint32_t smem0 = (uint32_t)__cvta_generic_to_shared(dynsmem);

    int tid = threadIdx.x;
    int lane = tid & 31, warp = tid >> 5;
    int wm = warp >> 2, wn = warp & 3;       // 2x4 warps, WM=64, WN=32
    int row0 = blockIdx.y * 128;
    int col0 = blockIdx.x * 128;

    float acc[4][4][4];
    #pragma unroll
    for (int i = 0; i < 4; ++i)
        #pragma unroll
        for (int j = 0; j < 4; ++j)
            #pragma unroll
            for (int c = 0; c < 4; ++c) acc[i][j][c] = 0.f;

    int crow = tid >> 1;
    int coff = (tid & 1) * 2;

    auto issue_copy = [&](int k0, int s) {
        uint32_t abase = smem0 + (uint32_t)(s * STG) * 4u;
        uint32_t bbase = abase + (uint32_t)ASZ * 4u;
        #pragma unroll
        for (int cc = 0; cc < 2; ++cc) {
            int off16 = coff + cc;
            cpasync16(abase + (uint32_t)(crow * 80 + off16 * 16),
                      Ag + (size_t)(row0 + crow) * lda + k0 + off16 * 8);
            cpasync16(bbase + (uint32_t)(crow * 80 + off16 * 16),
                      Bg + (size_t)(col0 + crow) * ldb + k0 + off16 * 8);
        }
    };

    issue_copy(0, 0);
    cp_commit();

    int nIter = Kdim / BK;
    for (int it = 0; it < nIter; ++it) {
        if (it + 1 < nIter) issue_copy((it + 1) * BK, (it + 1) & 1);
        cp_commit();
        cp_wait1();
        __syncthreads();

        const uint32_t* As = dynsmem + (it & 1) * STG;
        const uint32_t* Bs = As + ASZ;

        int ku = lane & 3;
        #pragma unroll
        for (int ks = 0; ks < 2; ++ks) {
            int kb = ks * 8;
            uint32_t af[4][4], bf[4][2];
            #pragma unroll
            for (int mt = 0; mt < 4; ++mt) {
                int mr = wm * 64 + mt * 16 + (lane >> 2);
                af[mt][0] = As[mr * RSTR + kb + ku];
                af[mt][1] = As[(mr + 8) * RSTR + kb + ku];
                af[mt][2] = As[mr * RSTR + kb + ku + 4];
                af[mt][3] = As[(mr + 8) * RSTR + kb + ku + 4];
            }
            #pragma unroll
            for (int nt = 0; nt < 4; ++nt) {
                int nc = wn * 32 + nt * 8 + (lane >> 2);
                bf[nt][0] = Bs[nc * RSTR + kb + ku];
                bf[nt][1] = Bs[nc * RSTR + kb + ku + 4];
            }
            #pragma unroll
            for (int mt = 0; mt < 4; ++mt)
                #pragma unroll
                for (int nt = 0; nt < 4; ++nt)
                    mma_bf16(acc[mt][nt][0], acc[mt][nt][1],
                             acc[mt][nt][2], acc[mt][nt][3],
                             af[mt][0], af[mt][1], af[mt][2], af[mt][3],
                             bf[nt][0], bf[nt][1]);
        }
        __syncthreads();
    }

    #pragma unroll
    for (int mt = 0; mt < 4; ++mt) {
        int mr = row0 + wm * 64 + mt * 16 + (lane >> 2);
        #pragma unroll
        for (int nt = 0; nt < 4; ++nt) {
            int nc = col0 + wn * 32 + nt * 8 + 2 * (lane & 3);
            *(float2*)(Cg + (size_t)mr * ldc + nc) =
                make_float2(acc[mt][nt][0], acc[mt][nt][1]);
            *(float2*)(Cg + (size_t)(mr + 8) * ldc + nc) =
                make_float2(acc[mt][nt][2], acc[mt][nt][3]);
        }
    }
}

// ---------------------------------------------------------------------------
// Top-16 candidates per row via packed u32 keys.
// Per-thread float top-8 scan (plain compares: scan indices increase, ties
// keep incumbent) -> pack to sortable u32 keys -> Batcher sort-8 ->
// 5 shuffle levels of bitonic top-8 merges (umax/umin) -> per-warp lists ->
// thread0 8-way merge -> 16 candidate indices.
// ---------------------------------------------------------------------------
__global__ __launch_bounds__(256) void topk16_kernel(
    const float* __restrict__ sim, int* __restrict__ cand) {
    __shared__ uint32_t swk[64];
    int row = blockIdx.x;
    int tid = threadIdx.x, lane = tid & 31, warp = tid >> 5;
    const float* s = sim + (size_t)row * NDICT;

    float tv[KP]; int ti[KP];
    #pragma unroll
    for (int i = 0; i < KP; ++i) { tv[i] = -3.4e38f; ti[i] = 0; }
    for (int j4 = tid; j4 < NDICT / 4; j4 += 256) {
        float4 v4 = *(const float4*)(s + (size_t)j4 * 4);
        float vv[4] = {v4.x, v4.y, v4.z, v4.w};
        #pragma unroll
        for (int cc = 0; cc < 4; ++cc) {
            float v = vv[cc];
            if (v > tv[KP - 1]) {            // ties keep incumbent (lower idx)
                int j = j4 * 4 + cc;
                int p = KP - 1;
                while (p > 0 && v > tv[p - 1]) {
                    tv[p] = tv[p - 1]; ti[p] = ti[p - 1]; --p;
                }
                tv[p] = v; ti[p] = j;
            }
        }
    }

    // pack to sortable keys + Batcher odd-even sort-8 (desc)
    uint32_t k[KP];
    #pragma unroll
    for (int i = 0; i < KP; ++i) k[i] = pack_key(tv[i], ti[i]);
    kswap(k[0], k[1]); kswap(k[2], k[3]); kswap(k[4], k[5]); kswap(k[6], k[7]);
    kswap(k[0], k[2]); kswap(k[1], k[3]); kswap(k[4], k[6]); kswap(k[5], k[7]);
    kswap(k[1], k[2]); kswap(k[5], k[6]);
    kswap(k[0], k[4]); kswap(k[1], k[5]); kswap(k[2], k[6]); kswap(k[3], k[7]);
    kswap(k[2], k[4]); kswap(k[3], k[5]);
    kswap(k[1], k[2]); kswap(k[3], k[4]); kswap(k[5], k[6]);

    // 5 shuffle levels: bitonic top-8-of-16 merge, all in u32 key domain
    #pragma unroll
    for (int off = 16; off >= 1; off >>= 1) {
        uint32_t ok[KP];
        #pragma unroll
        for (int i = 0; i < KP; ++i)
            ok[i] = __shfl_xor_sync(0xffffffffu, k[i], off);
        uint32_t c[KP];
        #pragma unroll
        for (int i = 0; i < KP; ++i) c[i] = umax(k[i], ok[KP - 1 - i]);
        // c is bitonic; sort desc with distances 4, 2, 1
        kswap(c[0], c[4]); kswap(c[1], c[5]); kswap(c[2], c[6]); kswap(c[3], c[7]);
        kswap(c[0], c[2]); kswap(c[1], c[3]); kswap(c[4], c[6]); kswap(c[5], c[7]);
        kswap(c[0], c[1]); kswap(c[2], c[3]); kswap(c[4], c[5]); kswap(c[6], c[7]);
        #pragma unroll
        for (int i = 0; i < KP; ++i) k[i] = c[i];
    }

    if (lane == 0) {
        #pragma unroll
        for (int i = 0; i < KP; ++i) swk[warp * KP + i] = k[i];
    }
    __syncthreads();

    // thread 0: 8-way merge of sorted key lists -> top-16 candidate indices
    if (tid == 0) {
        int ph[8];
        #pragma unroll
        for (int w = 0; w < 8; ++w) ph[w] = 0;
        for (int o = 0; o < KC; ++o) {
            int bw = 0; uint32_t bk = 0; bool have = false;
            #pragma unroll
            for (int w = 0; w < 8; ++w) {
                if (ph[w] < KP) {
                    uint32_t kk = swk[w * KP + ph[w]];
                    if (!have || kk > bk) { have = true; bw = w; bk = kk; }
                }
            }
            ph[bw]++;
            cand[(size_t)row * KC + o] = unpack_idx(bk);
        }
    }
}

// ---------------------------------------------------------------------------
// Exact fp32 rescore of the 16 candidates -> final top-8 indices.
// ---------------------------------------------------------------------------
__global__ __launch_bounds__(256) void rescore_kernel(
    const float* __restrict__ local, const float* __restrict__ gnorm,
    const int* __restrict__ cand, int* __restrict__ out) {
    __shared__ float t[D];
    __shared__ float cvv[KC];
    __shared__ int cii[KC];
    int row = blockIdx.x;
    int tid = threadIdx.x, lane = tid & 31, warp = tid >> 5;
    const float* tr = local + (size_t)row * D;
    #pragma unroll
    for (int i = 0; i < 3; ++i) t[tid + (i << 8)] = tr[tid + (i << 8)];
    if (tid < KC) cii[tid] = cand[(size_t)row * KC + tid];
    __syncthreads();

    #pragma unroll
    for (int cc = warp * 2; cc < warp * 2 + 2; ++cc) {
        const float* g = gnorm + (size_t)cii[cc] * D;
        float sum = 0.f;
        for (int j = lane; j < D; j += 32) sum += t[j] * g[j];
        #pragma unroll
        for (int o = 16; o >= 1; o >>= 1)
            sum += __shfl_xor_sync(0xffffffffu, sum, o);
        if (lane == 0) cvv[cc] = sum;
    }
    __syncthreads();

    if (tid == 0) {
        float tv[KP]; int ti[KP];
        #pragma unroll
        for (int i = 0; i < KP; ++i) { tv[i] = -3.4e38f; ti[i] = 0x7fffffff; }
        for (int cc = 0; cc < KC; ++cc) {
            float v = cvv[cc]; int j = cii[cc];
            if (tk_better(v, j, tv[KP - 1], ti[KP - 1])) {
                int p = KP - 1;
                while (p > 0 && tk_better(v, j, tv[p - 1], ti[p - 1])) {
                    tv[p] = tv[p - 1]; ti[p] = ti[p - 1]; --p;
                }
                tv[p] = v; ti[p] = j;
            }
        }
        #pragma unroll
        for (int i = 0; i < KP; ++i) out[(size_t)row * KP + i] = ti[i];
    }
}

// ---------------------------------------------------------------------------
// Multi-matrix NN projection GEMM: up to 4 (A, W, bias, C) sets per launch.
// ---------------------------------------------------------------------------
struct Ptrs4 {
    const float* A[4];
    const float* W[4];
    const float* bias[4];
    float* C[4];
};

__global__ __launch_bounds__(256) void tf32gemm_nn_multi(Ptrs4 p) {
    constexpr int BK = 32;
    constexpr int ASTR = 36;
    constexpr int ASZ = 128 * ASTR;
    constexpr int BSZ = 32 * 136;
    constexpr int STG = ASZ + BSZ;

    extern __shared__ uint32_t dynsmem[];
    uint32_t smem0 = (uint32_t)__cvta_generic_to_shared(dynsmem);

    int sel = blockIdx.x / 6;
    int col0 = (blockIdx.x % 6) * 128;
    const float* A = p.A[sel];
    const float* Bp = p.W[sel];
    const float* bias = p.bias[sel];
    float* C = p.C[sel];

    int tid = threadIdx.x;
    int lane = tid & 31, warp = tid >> 5;
    int wm = warp >> 2, wn = warp & 3;
    int row0 = blockIdx.y * 128;

    float acc[4][4][4];
    #pragma unroll
    for (int i = 0; i < 4; ++i)
        #pragma unroll
        for (int j = 0; j < 4; ++j)
            #pragma unroll
            for (int c = 0; c < 4; ++c) acc[i][j][c] = 0.f;

    int aK = tid & 7, aM = tid >> 3;
    int bN = tid & 31, bK = tid >> 5;

    auto issue_copy = [&](int k0, int s) {
        uint32_t abase = smem0 + (uint32_t)(s * STG) * 4u;
        #pragma unroll
        for (int mm = 0; mm < 128; mm += 32) {
            int r = mm + aM;
            cpasync16(abase + (uint32_t)(r * ASTR + aK * 4) * 4u,
                      A + (size_t)(row0 + r) * D + k0 + aK * 4);
        }
        uint32_t bbase = abase + (uint32_t)ASZ * 4u;
        #pragma unroll
        for (int kk = 0; kk < 32; kk += 8) {
            int r = kk + bK;
            cpasync16(bbase + (uint32_t)(r * 136 + bN * 4) * 4u,
                      Bp + (size_t)(k0 + r) * D + col0 + bN * 4);
        }
    };

    issue_copy(0, 0);
    cp_commit();

    int nIter = D / BK;     // 24
    for (int it = 0; it < nIter; ++it) {
        if (it + 1 < nIter) issue_copy((it + 1) * BK, (it + 1) & 1);
        cp_commit();
        cp_wait1();
        __syncthreads();

        const uint32_t* As = dynsmem + (it & 1) * STG;
        const uint32_t* Bs = As + ASZ;

        #pragma unroll
        for (int ks = 0; ks < 4; ++ks) {
            int kc = ks * 8 + (lane & 3);
            uint32_t af[4][4], bf[4][2];
            #pragma unroll
            for (int mt = 0; mt < 4; ++mt) {
                int mr = wm * 64 + mt * 16 + (lane >> 2);
                af[mt][0] = As[mr * ASTR + kc];
                af[mt][1] = As[(mr + 8) * ASTR + kc];
                af[mt][2] = As[mr * ASTR + kc + 4];
                af[mt][3] = As[(mr + 8) * ASTR + kc + 4];
            }
            #pragma unroll
            for (int nt = 0; nt < 4; ++nt) {
                int nc = wn * 32 + nt * 8 + (lane >> 2);
                bf[nt][0] = Bs[kc * 136 + nc];
                bf[nt][1] = Bs[(kc + 4) * 136 + nc];
            }
            #pragma unroll
            for (int mt = 0; mt < 4; ++mt)
                #pragma unroll
                for (int nt = 0; nt < 4; ++nt)
                    mma_tf32(acc[mt][nt][0], acc[mt][nt][1],
                             acc[mt][nt][2], acc[mt][nt][3],
                             af[mt][0], af[mt][1], af[mt][2], af[mt][3],
                             bf[nt][0], bf[nt][1]);
        }
        __syncthreads();
    }

    #pragma unroll
    for (int mt = 0; mt < 4; ++mt) {
        int mr = row0 + wm * 64 + mt * 16 + (lane >> 2);
        #pragma unroll
        for (int nt = 0; nt < 4; ++nt) {
            int nc = col0 + wn * 32 + nt * 8 + 2 * (lane & 3);
            float b0 = bias[nc], b1 = bias[nc + 1];
            *(float2*)(C + (size_t)mr * D + nc) =
                make_float2(acc[mt][nt][0] + b0, acc[mt][nt][1] + b1);
            *(float2*)(C + (size_t)(mr + 8) * D + nc) =
                make_float2(acc[mt][nt][2] + b0, acc[mt][nt][3] + b1);
        }
    }
}

// ---------------------------------------------------------------------------
// Fused flash attention per (b,h): ctx = softmax(Q K^T / 8) V
// ---------------------------------------------------------------------------
constexpr int FQ   = 128;
constexpr int FKV  = 64;
constexpr int QSTR = 68;
constexpr int VSTR = 72;
constexpr int F_QP = FQ * QSTR;
constexpr int F_K  = FKV * QSTR;
constexpr int F_V  = FKV * VSTR;
constexpr int FSMEM_BYTES = (F_QP + 2 * F_K + 2 * F_V) * 4;   // 106496

__global__ __launch_bounds__(256) void flash_kernel(
    const float* __restrict__ q, const float* __restrict__ k,
    const float* __restrict__ v, float* __restrict__ ctx, int Sk) {
    extern __shared__ float fsm[];
    uint32_t smem0 = (uint32_t)__cvta_generic_to_shared(fsm);

    int tid = threadIdx.x, lane = tid & 31, warp = tid >> 5;
    int q0 = blockIdx.x * FQ;
    int bh = blockIdx.y, b = bh / H, h = bh % H;
    const float* Qg = q + ((size_t)(b * L) + q0) * D + h * DH;
    const float* Kg = k + (size_t)b * Sk * D + h * DH;
    const float* Vg = v + (size_t)b * Sk * D + h * DH;

    int rbase = tid >> 4, c4 = (tid & 15) * 4;

    #pragma unroll
    for (int i = 0; i < 8; ++i) {
        int r = i * 16 + rbase;
        cpasync16(smem0 + (uint32_t)(r * QSTR + c4) * 4u, Qg + (size_t)r * D + c4);
    }
    auto ldK = [&](int it, int buf) {
        const float* src = Kg + (size_t)it * FKV * D;
        uint32_t base = smem0 + (uint32_t)(F_QP + buf * F_K) * 4u;
        #pragma unroll
        for (int i = 0; i < 4; ++i) {
            int r = i * 16 + rbase;
            cpasync16(base + (uint32_t)(r * QSTR + c4) * 4u, src + (size_t)r * D + c4);
        }
    };
    auto ldV = [&](int it, int buf) {
        const float* src = Vg + (size_t)it * FKV * D;
        uint32_t base = smem0 + (uint32_t)(F_QP + 2 * F_K + buf * F_V) * 4u;
        #pragma unroll
        for (int i = 0; i < 4; ++i) {
            int r = i * 16 + rbase;
            cpasync16(base + (uint32_t)(r * VSTR + c4) * 4u, src + (size_t)r * D + c4);
        }
    };
    ldK(0, 0); ldV(0, 0);
    cp_commit();
    cp_wait0();
    __syncthreads();

    int c = lane & 3, rq = lane >> 2;
    int prow = warp * 16 + rq;

    uint32_t qf[8][4];
    {
        const uint32_t* Qu = (const uint32_t*)fsm;
        #pragma unroll
        for (int kk = 0; kk < 8; ++kk) {
            qf[kk][0] = __float_as_uint(0.125f * __uint_as_float(Qu[prow * QSTR + kk * 8 + c]));
            qf[kk][1] = __float_as_uint(0.125f * __uint_as_float(Qu[(prow + 8) * QSTR + kk * 8 + c]));
            qf[kk][2] = __float_as_uint(0.125f * __uint_as_float(Qu[prow * QSTR + kk * 8 + c + 4]));
            qf[kk][3] = __float_as_uint(0.125f * __uint_as_float(Qu[(prow + 8) * QSTR + kk * 8 + c + 4]));
        }
    }
    __syncthreads();

    float of[8][4];
    #pragma unroll
    for (int nt = 0; nt < 8; ++nt)
        #pragma unroll
        for (int i = 0; i < 4; ++i) of[nt][i] = 0.f;
    float m0 = -3.0e38f, m1 = -3.0e38f, l0 = 0.f, l1 = 0.f;

    int nIter = Sk / FKV;
    for (int it = 0; it < nIter; ++it) {
        int cur = it & 1, nxt = cur ^ 1;
        if (it + 1 < nIter) { ldK(it + 1, nxt); ldV(it + 1, nxt); }
        cp_commit();

        const uint32_t* Ks = (const uint32_t*)fsm + F_QP + cur * F_K;
        const uint32_t* Vs = (const uint32_t*)fsm + F_QP + 2 * F_K + cur * F_V;

        float sf[8][4];
        #pragma unroll
        for (int nt = 0; nt < 8; ++nt)
            #pragma unroll
            for (int i = 0; i < 4; ++i) sf[nt][i] = 0.f;
        #pragma unroll
        for (int kk = 0; kk < 8; ++kk) {
            #pragma unroll
            for (int nt = 0; nt < 8; ++nt) {
                uint32_t b0 = Ks[(nt * 8 + rq) * QSTR + kk * 8 + c];
                uint32_t b1 = Ks[(nt * 8 + rq) * QSTR + kk * 8 + c + 4];
                mma_tf32(sf[nt][0], sf[nt][1], sf[nt][2], sf[nt][3],
                         qf[kk][0], qf[kk][1], qf[kk][2], qf[kk][3], b0, b1);
            }
        }

        float mx0 = -3.0e38f, mx1 = -3.0e38f;
        #pragma unroll
        for (int nt = 0; nt < 8; ++nt) {
            mx0 = fmaxf(mx0, fmaxf(sf[nt][0], sf[nt][1]));
            mx1 = fmaxf(mx1, fmaxf(sf[nt][2], sf[nt][3]));
        }
        mx0 = fmaxf(mx0, __shfl_xor_sync(0xffffffffu, mx0, 1));
        mx0 = fmaxf(mx0, __shfl_xor_sync(0xffffffffu, mx0, 2));
        mx1 = fmaxf(mx1, __shfl_xor_sync(0xffffffffu, mx1, 1));
        mx1 = fmaxf(mx1, __shfl_xor_sync(0xffffffffu, mx1, 2));
        float mn0 = fmaxf(m0, mx0), mn1 = fmaxf(m1, mx1);
        float f0 = __expf(m0 - mn0), f1 = __expf(m1 - mn1);

        float* Ps = fsm;
        float rs0 = 0.f, rs1 = 0.f;
        #pragma unroll
        for (int nt = 0; nt < 8; ++nt) {
            float p0 = __expf(sf[nt][0] - mn0);
            float p1 = __expf(sf[nt][1] - mn0);
            float p2 = __expf(sf[nt][2] - mn1);
            float p3 = __expf(sf[nt][3] - mn1);
            rs0 += p0 + p1; rs1 += p2 + p3;
            *(float2*)&Ps[prow * QSTR + nt * 8 + 2 * c] = make_float2(p0, p1);
            *(float2*)&Ps[(prow + 8) * QSTR + nt * 8 + 2 * c] = make_float2(p2, p3);
        }
        rs0 += __shfl_xor_sync(0xffffffffu, rs0, 1);
        rs0 += __shfl_xor_sync(0xffffffffu, rs0, 2);
        rs1 += __shfl_xor_sync(0xffffffffu, rs1, 1);
        rs1 += __shfl_xor_sync(0xffffffffu, rs1, 2);
        l0 = l0 * f0 + rs0; l1 = l1 * f1 + rs1;
        m0 = mn0; m1 = mn1;
        #pragma unroll
        for (int nt = 0; nt < 8; ++nt) {
            of[nt][0] *= f0; of[nt][1] *= f0;
            of[nt][2] *= f1; of[nt][3] *= f1;
        }
        __syncwarp();

        const uint32_t* Pu = (const uint32_t*)fsm;
        #pragma unroll
        for (int kk = 0; kk < 8; ++kk) {
            uint32_t a0 = Pu[prow * QSTR + kk * 8 + c];
            uint32_t a1 = Pu[(prow + 8) * QSTR + kk * 8 + c];
            uint32_t a2 = Pu[prow * QSTR + kk * 8 + c + 4];
            uint32_t a3 = Pu[(prow + 8) * QSTR + kk * 8 + c + 4];
            #pragma unroll
            for (int nt = 0; nt < 8; ++nt) {
                uint32_t b0 = Vs[(kk * 8 + c) * VSTR + nt * 8 + rq];
                uint32_t b1 = Vs[(kk * 8 + c + 4) * VSTR + nt * 8 + rq];
                mma_tf32(of[nt][0], of[nt][1], of[nt][2], of[nt][3],
                         a0, a1, a2, a3, b0, b1);
            }
        }
        cp_wait0();
        __syncthreads();
    }

    float il0 = 1.f / l0, il1 = 1.f / l1;
    int rg = b * L + q0 + warp * 16 + rq;
    float* dst0 = ctx + (size_t)rg * D + h * DH;
    float* dst1 = ctx + (size_t)(rg + 8) * D + h * DH;
    #pragma unroll
    for (int nt = 0; nt < 8; ++nt) {
        *(float2*)(dst0 + nt * 8 + 2 * c) = make_float2(of[nt][0] * il0, of[nt][1] * il0);
        *(float2*)(dst1 + nt * 8 + 2 * c) = make_float2(of[nt][2] * il1, of[nt][3] * il1);
    }
}

// ---------------------------------------------------------------------------
// Dict row L2-normalize: writes fp32 (for exact rescore) + bf16 (for GEMM)
// ---------------------------------------------------------------------------
__global__ __launch_bounds__(256) void rownorm_dual_kernel(
    const float* __restrict__ x, float* __restrict__ y,
    __nv_bfloat16* __restrict__ yb) {
    __shared__ float sh[256];
    size_t row = blockIdx.x;
    int tid = threadIdx.x;
    const float* xr = x + row * D;
    float* yr = y + row * D;
    __nv_bfloat16* ybr = yb + row * D;
    float v0 = xr[tid], v1 = xr[tid + 256], v2 = xr[tid + 512];
    float ss = blockReduceSum(v0 * v0 + v1 * v1 + v2 * v2, sh);
    float inv = rsqrtf(ss);
    float o0 = v0 * inv, o1 = v1 * inv, o2 = v2 * inv;
    yr[tid] = o0; yr[tid + 256] = o1; yr[tid + 512] = o2;
    ybr[tid] = __float2bfloat16(o0);
    ybr[tid + 256] = __float2bfloat16(o1);
    ybr[tid + 512] = __float2bfloat16(o2);
}

// ---------------------------------------------------------------------------
// fp32 -> bf16 convert (local feats, query side of sim GEMM)
// ---------------------------------------------------------------------------
__global__ __launch_bounds__(256) void tobf16_kernel(
    const float* __restrict__ x, __nv_bfloat16* __restrict__ y) {
    size_t base = (size_t)blockIdx.x * D;
    int tid = threadIdx.x;
    #pragma unroll
    for (int i = 0; i < 3; ++i) {
        int j = tid + (i << 8);
        y[base + j] = __float2bfloat16(x[base + j]);
    }
}

// ---------------------------------------------------------------------------
// Gather retrieved prototypes (UNnormalized dict rows) into [B*SKG, D]
// ---------------------------------------------------------------------------
__global__ __launch_bounds__(256) void gather_kernel(
    const float* __restrict__ dict, const int* __restrict__ topk,
    float* __restrict__ gfeats) {
    int r = blockIdx.x;
    int b = r >> 11;
    int pos = r & 2047;
    int idx = topk[((size_t)(b * L + (pos >> 3))) * KP + (pos & 7)];
    const float* src = dict + (size_t)idx * D;
    float* dst = gfeats + (size_t)r * D;
    for (int j = threadIdx.x; j < D / 4; j += 256)
        ((float4*)dst)[j] = ((const float4*)src)[j];
}

// ---------------------------------------------------------------------------
// Fused tail: ll = LN(proj+local), lg = LN(proj2+local), o = LN(ll+lg),
// gate = sigmoid(o.aug_w + aug_b + local.ori_w + ori_b),
// out = gate*o + (1-gate)*local
// ---------------------------------------------------------------------------
__global__ __launch_bounds__(256) void tail_kernel(
    const float* __restrict__ proj, const float* __restrict__ proj2,
    const float* __restrict__ local,
    const float* __restrict__ g0, const float* __restrict__ b0,
    const float* __restrict__ g1, const float* __restrict__ b1,
    const float* __restrict__ g2, const float* __restrict__ b2,
    const float* __restrict__ aug_w, const float* __restrict__ aug_b,
    const float* __restrict__ ori_w, const float* __restrict__ ori_b,
    float* __restrict__ out) {
    __shared__ float sh[256];
    size_t base = (size_t)blockIdx.x * D;
    int tid = threadIdx.x;
    float a[3], bb[3], lf[3];
    #pragma unroll
    for (int t = 0; t < 3; ++t) {
        int i = tid + (t << 8);
        lf[t] = local[base + i];
        a[t] = proj[base + i] + lf[t];
        bb[t] = proj2[base + i] + lf[t];
    }
    float mean = blockReduceSum(a[0] + a[1] + a[2], sh) * (1.0f / 768.0f);
    float d0 = a[0] - mean, d1 = a[1] - mean, d2 = a[2] - mean;
    float var = blockReduceSum(d0 * d0 + d1 * d1 + d2 * d2, sh) * (1.0f / 768.0f);
    float inv = rsqrtf(var + 1e-12f);
    float llv[3];
    #pragma unroll
    for (int t = 0; t < 3; ++t) {
        int i = tid + (t << 8);
        llv[t] = (a[t] - mean) * inv * g0[i] + b0[i];
    }
    mean = blockReduceSum(bb[0] + bb[1] + bb[2], sh) * (1.0f / 768.0f);
    d0 = bb[0] - mean; d1 = bb[1] - mean; d2 = bb[2] - mean;
    var = blockReduceSum(d0 * d0 + d1 * d1 + d2 * d2, sh) * (1.0f / 768.0f);
    inv = rsqrtf(var + 1e-12f);
    float s[3];
    #pragma unroll
    for (int t = 0; t < 3; ++t) {
        int i = tid + (t << 8);
        s[t] = llv[t] + (bb[t] - mean) * inv * g1[i] + b1[i];
    }
    mean = blockReduceSum(s[0] + s[1] + s[2], sh) * (1.0f / 768.0f);
    d0 = s[0] - mean; d1 = s[1] - mean; d2 = s[2] - mean;
    var = blockReduceSum(d0 * d0 + d1 * d1 + d2 * d2, sh) * (1.0f / 768.0f);
    inv = rsqrtf(var + 1e-12f);
    float o[3];
    float dsum = 0.f;
    #pragma unroll
    for (int t = 0; t < 3; ++t) {
        int i = tid + (t << 8);
        o[t] = (s[t] - mean) * inv * g2[i] + b2[i];
        dsum += o[t] * aug_w[i] + lf[t] * ori_w[i];
    }
    dsum = blockReduceSum(dsum, sh);
    float gate = 1.0f / (1.0f + expf(-(dsum + aug_b[0] + ori_b[0])));
    #pragma unroll
    for (int t = 0; t < 3; ++t) {
        int i = tid + (t << 8);
        out[base + i] = gate * o[t] + (1.0f - gate) * lf[t];
    }
}

// ---------------------------------------------------------------------------
// Host launcher
// ---------------------------------------------------------------------------
extern "C" void kernel_launch(void* const* d_in, const int* in_sizes, int n_in,
                              void* d_out, int out_size) {
    (void)n_in; (void)out_size;
    const float* local = (const float*)d_in[0];
    const float* dict  = (const float*)d_in[1];

    bool sig = (in_sizes[3] == 768);
    const float *W[2][4], *Bi[2][4], *LNG[2], *LNB[2];
    for (int p = 0; p < 2; ++p) {
        int base = 2 + p * 10;
        if (sig) {
            for (int j = 0; j < 4; ++j) {
                W[p][j]  = (const float*)d_in[base + 2 * j];
                Bi[p][j] = (const float*)d_in[base + 2 * j + 1];
            }
        } else {
            for (int j = 0; j < 4; ++j) {
                W[p][j]  = (const float*)d_in[base + j];
                Bi[p][j] = (const float*)d_in[base + 4 + j];
            }
        }
        LNG[p] = (const float*)d_in[base + 8];
        LNB[p] = (const float*)d_in[base + 9];
    }
    const float* ln_g = (const float*)d_in[22];
    const float* ln_b = (const float*)d_in[23];
    const float *aug_w, *aug_b, *ori_w, *ori_b;
    if (in_sizes[25] == 1) {
        aug_w = (const float*)d_in[24]; aug_b = (const float*)d_in[25];
        ori_w = (const float*)d_in[26]; ori_b = (const float*)d_in[27];
    } else {
        aug_w = (const float*)d_in[24]; ori_w = (const float*)d_in[25];
        aug_b = (const float*)d_in[26]; ori_b = (const float*)d_in[27];
    }

    float *p_gnorm, *p_sim, *p_gfeats, *p_q, *p_q2, *p_k, *p_v;
    float *p_ctx, *p_ctx2, *p_proj, *p_proj2;
    __nv_bfloat16 *p_gnorm_bf, *p_local_bf;
    int *p_cand, *p_topk;
    cudaGetSymbolAddress((void**)&p_gnorm, g_gnorm);
    cudaGetSymbolAddress((void**)&p_gnorm_bf, g_gnorm_bf);
    cudaGetSymbolAddress((void**)&p_local_bf, g_local_bf);
    cudaGetSymbolAddress((void**)&p_sim, g_sim);
    cudaGetSymbolAddress((void**)&p_cand, g_cand);
    cudaGetSymbolAddress((void**)&p_topk, g_topk);
    cudaGetSymbolAddress((void**)&p_gfeats, g_gfeats);
    cudaGetSymbolAddress((void**)&p_q, g_q);
    cudaGetSymbolAddress((void**)&p_q2, g_q2);
    cudaGetSymbolAddress((void**)&p_k, g_k);
    cudaGetSymbolAddress((void**)&p_v, g_v);
    cudaGetSymbolAddress((void**)&p_ctx, g_ctx);
    cudaGetSymbolAddress((void**)&p_ctx2, g_ctx2);
    cudaGetSymbolAddress((void**)&p_proj, g_proj);
    cudaGetSymbolAddress((void**)&p_proj2, g_proj2);

    const int SM_BF  = 2 * (2 * 128 * 20) * 4;          // 40960 (bf16 sim)
    const int SM_NN  = 2 * (128 * 36 + 32 * 136) * 4;   // 71680

    cudaFuncSetAttribute(bf16gemm_nt,
                         cudaFuncAttributeMaxDynamicSharedMemorySize, SM_BF);
    cudaFuncSetAttribute(tf32gemm_nn_multi,
                         cudaFuncAttributeMaxDynamicSharedMemorySize, SM_NN);
    cudaFuncSetAttribute(flash_kernel,
                         cudaFuncAttributeMaxDynamicSharedMemorySize, FSMEM_BYTES);

    // 1) normalize dict rows (fp32 + bf16); convert local feats to bf16
    rownorm_dual_kernel<<<NDICT, 256>>>(dict, p_gnorm, p_gnorm_bf);
    tobf16_kernel<<<M, 256>>>(local, p_local_bf);

    // 2) approx sim = local_bf @ gnorm_bf^T (bf16 MMA, fp32 accum)
    bf16gemm_nt<<<dim3(NDICT / 128, M / 128), 256, SM_BF>>>(
        p_local_bf, p_gnorm_bf, p_sim, D, D, D, NDICT);

    // 3) packed-key top-16 candidates -> exact fp32 rescore -> top-8 -> gather
    topk16_kernel<<<M, 256>>>(p_sim, p_cand);
    rescore_kernel<<<M, 256>>>(local, p_gnorm, p_cand, p_topk);
    gather_kernel<<<B * SKG, 256>>>(dict, p_topk, p_gfeats);

    // 4) merged small projections: ll Q,K,V + lg Q (all read `local`)
    {
        Ptrs4 p;
        p.A[0] = local;    p.A[1] = local;    p.A[2] = local;    p.A[3] = local;
        p.W[0] = W[0][0];  p.W[1] = W[0][1];  p.W[2] = W[0][2];  p.W[3] = W[1][0];
        p.bias[0] = Bi[0][0]; p.bias[1] = Bi[0][1]; p.bias[2] = Bi[0][2]; p.bias[3] = Bi[1][0];
        p.C[0] = p_q;      p.C[1] = p_k;      p.C[2] = p_v;      p.C[3] = p_q2;
        tf32gemm_nn_multi<<<dim3(24, M / 128), 256, SM_NN>>>(p);
    }

    // 5) ll fused attention
    flash_kernel<<<dim3(L / FQ, BH), 256, FSMEM_BYTES>>>(p_q, p_k, p_v, p_ctx, L);

    // 6) lg K,V projections over gathered prototypes
    {
        Ptrs4 p;
        p.A[0] = p_gfeats; p.A[1] = p_gfeats; p.A[2] = p_gfeats; p.A[3] = p_gfeats;
        p.W[0] = W[1][1];  p.W[1] = W[1][2];  p.W[2] = W[1][1];  p.W[3] = W[1][2];
        p.bias[0] = Bi[1][1]; p.bias[1] = Bi[1][2]; p.bias[2] = Bi[1][1]; p.bias[3] = Bi[1][2];
        p.C[0] = p_k;      p.C[1] = p_v;      p.C[2] = p_k;      p.C[3] = p_v;
        tf32gemm_nn_multi<<<dim3(12, (B * SKG) / 128), 256, SM_NN>>>(p);
    }

    // 7) lg fused attention
    flash_kernel<<<dim3(L / FQ, BH), 256, FSMEM_BYTES>>>(p_q2, p_k, p_v, p_ctx2, SKG);

    // 8) merged output projections
    {
        Ptrs4 p;
        p.A[0] = p_ctx;    p.A[1] = p_ctx2;   p.A[2] = p_ctx;    p.A[3] = p_ctx2;
        p.W[0] = W[0][3];  p.W[1] = W[1][3];  p.W[2] = W[0][3];  p.W[3] = W[1][3];
        p.bias[0] = Bi[0][3]; p.bias[1] = Bi[1][3]; p.bias[2] = Bi[0][3]; p.bias[3] = Bi[1][3];
        p.C[0] = p_proj;   p.C[1] = p_proj2;  p.C[2] = p_proj;   p.C[3] = p_proj2;
        tf32gemm_nn_multi<<<dim3(12, M / 128), 256, SM_NN>>>(p);
    }

    // 9) fused tail: both residual LNs + final LN + gating
    tail_kernel<<<M, 256>>>(p_proj, p_proj2, local,
                            LNG[0], LNB[0], LNG[1], LNB[1], ln_g, ln_b,
                            aug_w, aug_b, ori_w, ori_b, (float*)d_out);
}

// round 17
// speedup vs baseline: 1.7690x; 1.7690x over previous
#include <cuda_runtime.h>
#include <cuda_bf16.h>
#include <cstdint>

// ---------------------------------------------------------------------------
// Problem constants
// ---------------------------------------------------------------------------
constexpr int B     = 8;
constexpr int L     = 256;
constexpr int D     = 768;
constexpr int H     = 12;
constexpr int DH    = 64;          // D / H
constexpr int M     = B * L;       // 2048 total query rows
constexpr int NDICT = 16384;
constexpr int KP    = 8;           // final top-k
constexpr int KC    = 16;          // candidate count from approx sim
constexpr int SKG   = L * KP;      // 2048 kv rows per batch (cross-attn)
constexpr int BH    = B * H;       // 96

// ---------------------------------------------------------------------------
// Device-global scratch (no dynamic allocation allowed)
// ---------------------------------------------------------------------------
__device__ __align__(16) float g_gnorm[(size_t)NDICT * D];
__device__ __align__(16) __nv_bfloat16 g_gnorm_bf[(size_t)NDICT * D];
__device__ __align__(16) __nv_bfloat16 g_local_bf[(size_t)M * D];
__device__ __align__(16) float g_sim[(size_t)M * NDICT];
__device__ int   g_cand[(size_t)M * KC];
__device__ int   g_topk[(size_t)M * KP];
__device__ __align__(16) __nv_bfloat16 g_gfeats_bf[(size_t)B * SKG * D];
__device__ __align__(16) __nv_bfloat16 g_wkt[(size_t)D * D];
__device__ __align__(16) __nv_bfloat16 g_wvt[(size_t)D * D];
__device__ __align__(16) float g_q[(size_t)M * D];
__device__ __align__(16) float g_q2[(size_t)M * D];
__device__ __align__(16) float g_k[(size_t)B * SKG * D];
__device__ __align__(16) float g_v[(size_t)B * SKG * D];
__device__ __align__(16) float g_ctx[(size_t)M * D];
__device__ __align__(16) float g_ctx2[(size_t)M * D];
__device__ __align__(16) float g_proj[(size_t)M * D];
__device__ __align__(16) float g_proj2[(size_t)M * D];

#define DEV_INLINE __device__ __forceinline__

DEV_INLINE float blockReduceSum(float v, float* sh) {
    int tid = threadIdx.x;
    sh[tid] = v; __syncthreads();
    #pragma unroll
    for (int s = 128; s > 0; s >>= 1) {
        if (tid < s) sh[tid] += sh[tid + s];
        __syncthreads();
    }
    float r = sh[0]; __syncthreads();
    return r;
}

// jax.lax.top_k order: value desc, ties -> lower index first.
DEV_INLINE bool tk_better(float v, int i, float tv, int ti) {
    return (v > tv) || (v == tv && i < ti);
}

// ---------------------------------------------------------------------------
// mma + cp.async helpers
// ---------------------------------------------------------------------------
DEV_INLINE void mma_tf32(float& c0, float& c1, float& c2, float& c3,
                         uint32_t a0, uint32_t a1, uint32_t a2, uint32_t a3,
                         uint32_t b0, uint32_t b1) {
    asm volatile(
        "mma.sync.aligned.m16n8k8.row.col.f32.tf32.tf32.f32 "
        "{%0,%1,%2,%3}, {%4,%5,%6,%7}, {%8,%9}, {%0,%1,%2,%3};"
        : "+f"(c0), "+f"(c1), "+f"(c2), "+f"(c3)
        : "r"(a0), "r"(a1), "r"(a2), "r"(a3), "r"(b0), "r"(b1));
}

DEV_INLINE void mma_bf16(float& c0, float& c1, float& c2, float& c3,
                         uint32_t a0, uint32_t a1, uint32_t a2, uint32_t a3,
                         uint32_t b0, uint32_t b1) {
    asm volatile(
        "mma.sync.aligned.m16n8k16.row.col.f32.bf16.bf16.f32 "
        "{%0,%1,%2,%3}, {%4,%5,%6,%7}, {%8,%9}, {%0,%1,%2,%3};"
        : "+f"(c0), "+f"(c1), "+f"(c2), "+f"(c3)
        : "r"(a0), "r"(a1), "r"(a2), "r"(a3), "r"(b0), "r"(b1));
}

DEV_INLINE void cpasync16(uint32_t dst_smem_bytes, const void* src) {
    asm volatile("cp.async.cg.shared.global [%0], [%1], 16;\n"
                 :: "r"(dst_smem_bytes), "l"(src));
}
DEV_INLINE void cp_commit() { asm volatile("cp.async.commit_group;\n" ::); }
DEV_INLINE void cp_wait1()  { asm volatile("cp.async.wait_group 1;\n" ::); }
DEV_INLINE void cp_wait0()  { asm volatile("cp.async.wait_group 0;\n" ::); }

// ---------------------------------------------------------------------------
// bf16 NT GEMM: C[m,n] = A[m,:].B[n,:] (+ bias[n]).  A:[M,K], B:[N,K] bf16.
// fp32 accum/output. BM=BN=128, BK=32, 256 threads, 2-stage cp.async.
// ---------------------------------------------------------------------------
template <bool HAS_BIAS>
__global__ __launch_bounds__(256) void bf16gemm_nt(
    const __nv_bfloat16* __restrict__ Ag, const __nv_bfloat16* __restrict__ Bg,
    const float* __restrict__ bias, float* __restrict__ Cg,
    int Kdim, int lda, int ldb, int ldc) {
    constexpr int BK = 32;
    constexpr int RSTR = 20;                 // u32 per row (80 bytes)
    constexpr int ASZ = 128 * RSTR;          // 2560 u32
    constexpr int STG = 2 * ASZ;             // A + B

    extern __shared__ uint32_t dynsmem[];
    uint32_t smem0 = (uint32_t)__cvta_generic_to_shared(dynsmem);

    int tid = threadIdx.x;
    int lane = tid & 31, warp = tid >> 5;
    int wm = warp >> 2, wn = warp & 3;       // 2x4 warps, WM=64, WN=32
    int row0 = blockIdx.y * 128;
    int col0 = blockIdx.x * 128;

    float acc[4][4][4];
    #pragma unroll
    for (int i = 0; i < 4; ++i)
        #pragma unroll
        for (int j = 0; j < 4; ++j)
            #pragma unroll
            for (int c = 0; c < 4; ++c) acc[i][j][c] = 0.f;

    int crow = tid >> 1;
    int coff = (tid & 1) * 2;

    auto issue_copy = [&](int k0, int s) {
        uint32_t abase = smem0 + (uint32_t)(s * STG) * 4u;
        uint32_t bbase = abase + (uint32_t)ASZ * 4u;
        #pragma unroll
        for (int cc = 0; cc < 2; ++cc) {
            int off16 = coff + cc;
            cpasync16(abase + (uint32_t)(crow * 80 + off16 * 16),
                      Ag + (size_t)(row0 + crow) * lda + k0 + off16 * 8);
            cpasync16(bbase + (uint32_t)(crow * 80 + off16 * 16),
                      Bg + (size_t)(col0 + crow) * ldb + k0 + off16 * 8);
        }
    };

    issue_copy(0, 0);
    cp_commit();

    int nIter = Kdim / BK;
    for (int it = 0; it < nIter; ++it) {
        if (it + 1 < nIter) issue_copy((it + 1) * BK, (it + 1) & 1);
        cp_commit();
        cp_wait1();
        __syncthreads();

        const uint32_t* As = dynsmem + (it & 1) * STG;
        const uint32_t* Bs = As + ASZ;

        int ku = lane & 3;
        #pragma unroll
        for (int ks = 0; ks < 2; ++ks) {
            int kb = ks * 8;
            uint32_t af[4][4], bf[4][2];
            #pragma unroll
            for (int mt = 0; mt < 4; ++mt) {
                int mr = wm * 64 + mt * 16 + (lane >> 2);
                af[mt][0] = As[mr * RSTR + kb + ku];
                af[mt][1] = As[(mr + 8) * RSTR + kb + ku];
                af[mt][2] = As[mr * RSTR + kb + ku + 4];
                af[mt][3] = As[(mr + 8) * RSTR + kb + ku + 4];
            }
            #pragma unroll
            for (int nt = 0; nt < 4; ++nt) {
                int nc = wn * 32 + nt * 8 + (lane >> 2);
                bf[nt][0] = Bs[nc * RSTR + kb + ku];
                bf[nt][1] = Bs[nc * RSTR + kb + ku + 4];
            }
            #pragma unroll
            for (int mt = 0; mt < 4; ++mt)
                #pragma unroll
                for (int nt = 0; nt < 4; ++nt)
                    mma_bf16(acc[mt][nt][0], acc[mt][nt][1],
                             acc[mt][nt][2], acc[mt][nt][3],
                             af[mt][0], af[mt][1], af[mt][2], af[mt][3],
                             bf[nt][0], bf[nt][1]);
        }
        __syncthreads();
    }

    #pragma unroll
    for (int mt = 0; mt < 4; ++mt) {
        int mr = row0 + wm * 64 + mt * 16 + (lane >> 2);
        #pragma unroll
        for (int nt = 0; nt < 4; ++nt) {
            int nc = col0 + wn * 32 + nt * 8 + 2 * (lane & 3);
            float b0 = 0.f, b1 = 0.f;
            if (HAS_BIAS) { b0 = bias[nc]; b1 = bias[nc + 1]; }
            *(float2*)(Cg + (size_t)mr * ldc + nc) =
                make_float2(acc[mt][nt][0] + b0, acc[mt][nt][1] + b1);
            *(float2*)(Cg + (size_t)(mr + 8) * ldc + nc) =
                make_float2(acc[mt][nt][2] + b0, acc[mt][nt][3] + b1);
        }
    }
}

// ---------------------------------------------------------------------------
// Top-16 candidates per row (R13 version: float scan + warp-shuffle bitonic).
// ---------------------------------------------------------------------------
DEV_INLINE void cswap(float& va, int& ia, float& vb, int& ib) {
    if (tk_better(vb, ib, va, ia)) {
        float tv = va; va = vb; vb = tv;
        int t = ia; ia = ib; ib = t;
    }
}

__global__ __launch_bounds__(256) void topk16_kernel(
    const float* __restrict__ sim, int* __restrict__ cand) {
    __shared__ float swv[64];
    __shared__ int   swi[64];
    int row = blockIdx.x;
    int tid = threadIdx.x, lane = tid & 31, warp = tid >> 5;
    const float* s = sim + (size_t)row * NDICT;

    float tv[KP]; int ti[KP];
    #pragma unroll
    for (int i = 0; i < KP; ++i) { tv[i] = -3.4e38f; ti[i] = 0x7fffffff; }
    for (int j4 = tid; j4 < NDICT / 4; j4 += 256) {
        float4 v4 = *(const float4*)(s + (size_t)j4 * 4);
        float vv[4] = {v4.x, v4.y, v4.z, v4.w};
        #pragma unroll
        for (int cc = 0; cc < 4; ++cc) {
            float v = vv[cc];
            int j = j4 * 4 + cc;
            if (tk_better(v, j, tv[KP - 1], ti[KP - 1])) {
                int p = KP - 1;
                while (p > 0 && tk_better(v, j, tv[p - 1], ti[p - 1])) {
                    tv[p] = tv[p - 1]; ti[p] = ti[p - 1]; --p;
                }
                tv[p] = v; ti[p] = j;
            }
        }
    }

    // 5 shuffle levels: merge sorted-desc 8-lists, keep top-8 (bitonic).
    #pragma unroll
    for (int off = 16; off >= 1; off >>= 1) {
        float ov[KP]; int oi[KP];
        #pragma unroll
        for (int i = 0; i < KP; ++i) {
            ov[i] = __shfl_xor_sync(0xffffffffu, tv[i], off);
            oi[i] = __shfl_xor_sync(0xffffffffu, ti[i], off);
        }
        float c[KP]; int ci[KP];
        #pragma unroll
        for (int i = 0; i < KP; ++i) {
            if (tk_better(tv[i], ti[i], ov[KP - 1 - i], oi[KP - 1 - i])) {
                c[i] = tv[i]; ci[i] = ti[i];
            } else {
                c[i] = ov[KP - 1 - i]; ci[i] = oi[KP - 1 - i];
            }
        }
        cswap(c[0], ci[0], c[4], ci[4]);
        cswap(c[1], ci[1], c[5], ci[5]);
        cswap(c[2], ci[2], c[6], ci[6]);
        cswap(c[3], ci[3], c[7], ci[7]);
        cswap(c[0], ci[0], c[2], ci[2]);
        cswap(c[1], ci[1], c[3], ci[3]);
        cswap(c[4], ci[4], c[6], ci[6]);
        cswap(c[5], ci[5], c[7], ci[7]);
        cswap(c[0], ci[0], c[1], ci[1]);
        cswap(c[2], ci[2], c[3], ci[3]);
        cswap(c[4], ci[4], c[5], ci[5]);
        cswap(c[6], ci[6], c[7], ci[7]);
        #pragma unroll
        for (int i = 0; i < KP; ++i) { tv[i] = c[i]; ti[i] = ci[i]; }
    }

    if (lane == 0) {
        #pragma unroll
        for (int i = 0; i < KP; ++i) {
            swv[warp * KP + i] = tv[i];
            swi[warp * KP + i] = ti[i];
        }
    }
    __syncthreads();

    // thread 0: 8-way merge of sorted lists -> top-16 candidates
    if (tid == 0) {
        int ph[8];
        #pragma unroll
        for (int w = 0; w < 8; ++w) ph[w] = 0;
        for (int o = 0; o < KC; ++o) {
            int bw = -1; float bv = -3.4e38f; int bi = 0x7fffffff;
            #pragma unroll
            for (int w = 0; w < 8; ++w) {
                if (ph[w] < KP) {
                    float v = swv[w * KP + ph[w]];
                    int idx = swi[w * KP + ph[w]];
                    if (bw < 0 || tk_better(v, idx, bv, bi)) {
                        bw = w; bv = v; bi = idx;
                    }
                }
            }
            ph[bw]++;
            cand[(size_t)row * KC + o] = bi;
        }
    }
}

// ---------------------------------------------------------------------------
// Exact fp32 rescore of the 16 candidates -> final top-8 indices.
// ---------------------------------------------------------------------------
__global__ __launch_bounds__(256) void rescore_kernel(
    const float* __restrict__ local, const float* __restrict__ gnorm,
    const int* __restrict__ cand, int* __restrict__ out) {
    __shared__ float t[D];
    __shared__ float cvv[KC];
    __shared__ int cii[KC];
    int row = blockIdx.x;
    int tid = threadIdx.x, lane = tid & 31, warp = tid >> 5;
    const float* tr = local + (size_t)row * D;
    #pragma unroll
    for (int i = 0; i < 3; ++i) t[tid + (i << 8)] = tr[tid + (i << 8)];
    if (tid < KC) cii[tid] = cand[(size_t)row * KC + tid];
    __syncthreads();

    #pragma unroll
    for (int cc = warp * 2; cc < warp * 2 + 2; ++cc) {
        const float* g = gnorm + (size_t)cii[cc] * D;
        float sum = 0.f;
        for (int j = lane; j < D; j += 32) sum += t[j] * g[j];
        #pragma unroll
        for (int o = 16; o >= 1; o >>= 1)
            sum += __shfl_xor_sync(0xffffffffu, sum, o);
        if (lane == 0) cvv[cc] = sum;
    }
    __syncthreads();

    if (tid == 0) {
        float tv[KP]; int ti[KP];
        #pragma unroll
        for (int i = 0; i < KP; ++i) { tv[i] = -3.4e38f; ti[i] = 0x7fffffff; }
        for (int cc = 0; cc < KC; ++cc) {
            float v = cvv[cc]; int j = cii[cc];
            if (tk_better(v, j, tv[KP - 1], ti[KP - 1])) {
                int p = KP - 1;
                while (p > 0 && tk_better(v, j, tv[p - 1], ti[p - 1])) {
                    tv[p] = tv[p - 1]; ti[p] = ti[p - 1]; --p;
                }
                tv[p] = v; ti[p] = j;
            }
        }
        #pragma unroll
        for (int i = 0; i < KP; ++i) out[(size_t)row * KP + i] = ti[i];
    }
}

// ---------------------------------------------------------------------------
// Multi-matrix NN projection GEMM: up to 4 (A, W, bias, C) sets per launch.
// ---------------------------------------------------------------------------
struct Ptrs4 {
    const float* A[4];
    const float* W[4];
    const float* bias[4];
    float* C[4];
};

__global__ __launch_bounds__(256) void tf32gemm_nn_multi(Ptrs4 p) {
    constexpr int BK = 32;
    constexpr int ASTR = 36;
    constexpr int ASZ = 128 * ASTR;
    constexpr int BSZ = 32 * 136;
    constexpr int STG = ASZ + BSZ;

    extern __shared__ uint32_t dynsmem[];
    uint32_t smem0 = (uint32_t)__cvta_generic_to_shared(dynsmem);

    int sel = blockIdx.x / 6;
    int col0 = (blockIdx.x % 6) * 128;
    const float* A = p.A[sel];
    const float* Bp = p.W[sel];
    const float* bias = p.bias[sel];
    float* C = p.C[sel];

    int tid = threadIdx.x;
    int lane = tid & 31, warp = tid >> 5;
    int wm = warp >> 2, wn = warp & 3;
    int row0 = blockIdx.y * 128;

    float acc[4][4][4];
    #pragma unroll
    for (int i = 0; i < 4; ++i)
        #pragma unroll
        for (int j = 0; j < 4; ++j)
            #pragma unroll
            for (int c = 0; c < 4; ++c) acc[i][j][c] = 0.f;

    int aK = tid & 7, aM = tid >> 3;
    int bN = tid & 31, bK = tid >> 5;

    auto issue_copy = [&](int k0, int s) {
        uint32_t abase = smem0 + (uint32_t)(s * STG) * 4u;
        #pragma unroll
        for (int mm = 0; mm < 128; mm += 32) {
            int r = mm + aM;
            cpasync16(abase + (uint32_t)(r * ASTR + aK * 4) * 4u,
                      A + (size_t)(row0 + r) * D + k0 + aK * 4);
        }
        uint32_t bbase = abase + (uint32_t)ASZ * 4u;
        #pragma unroll
        for (int kk = 0; kk < 32; kk += 8) {
            int r = kk + bK;
            cpasync16(bbase + (uint32_t)(r * 136 + bN * 4) * 4u,
                      Bp + (size_t)(k0 + r) * D + col0 + bN * 4);
        }
    };

    issue_copy(0, 0);
    cp_commit();

    int nIter = D / BK;     // 24
    for (int it = 0; it < nIter; ++it) {
        if (it + 1 < nIter) issue_copy((it + 1) * BK, (it + 1) & 1);
        cp_commit();
        cp_wait1();
        __syncthreads();

        const uint32_t* As = dynsmem + (it & 1) * STG;
        const uint32_t* Bs = As + ASZ;

        #pragma unroll
        for (int ks = 0; ks < 4; ++ks) {
            int kc = ks * 8 + (lane & 3);
            uint32_t af[4][4], bf[4][2];
            #pragma unroll
            for (int mt = 0; mt < 4; ++mt) {
                int mr = wm * 64 + mt * 16 + (lane >> 2);
                af[mt][0] = As[mr * ASTR + kc];
                af[mt][1] = As[(mr + 8) * ASTR + kc];
                af[mt][2] = As[mr * ASTR + kc + 4];
                af[mt][3] = As[(mr + 8) * ASTR + kc + 4];
            }
            #pragma unroll
            for (int nt = 0; nt < 4; ++nt) {
                int nc = wn * 32 + nt * 8 + (lane >> 2);
                bf[nt][0] = Bs[kc * 136 + nc];
                bf[nt][1] = Bs[(kc + 4) * 136 + nc];
            }
            #pragma unroll
            for (int mt = 0; mt < 4; ++mt)
                #pragma unroll
                for (int nt = 0; nt < 4; ++nt)
                    mma_tf32(acc[mt][nt][0], acc[mt][nt][1],
                             acc[mt][nt][2], acc[mt][nt][3],
                             af[mt][0], af[mt][1], af[mt][2], af[mt][3],
                             bf[nt][0], bf[nt][1]);
        }
        __syncthreads();
    }

    #pragma unroll
    for (int mt = 0; mt < 4; ++mt) {
        int mr = row0 + wm * 64 + mt * 16 + (lane >> 2);
        #pragma unroll
        for (int nt = 0; nt < 4; ++nt) {
            int nc = col0 + wn * 32 + nt * 8 + 2 * (lane & 3);
            float b0 = bias[nc], b1 = bias[nc + 1];
            *(float2*)(C + (size_t)mr * D + nc) =
                make_float2(acc[mt][nt][0] + b0, acc[mt][nt][1] + b1);
            *(float2*)(C + (size_t)(mr + 8) * D + nc) =
                make_float2(acc[mt][nt][2] + b0, acc[mt][nt][3] + b1);
        }
    }
}

// ---------------------------------------------------------------------------
// Fused flash attention per (b,h): ctx = softmax(Q K^T / 8) V
// ---------------------------------------------------------------------------
constexpr int FQ   = 128;
constexpr int FKV  = 64;
constexpr int QSTR = 68;
constexpr int VSTR = 72;
constexpr int F_QP = FQ * QSTR;
constexpr int F_K  = FKV * QSTR;
constexpr int F_V  = FKV * VSTR;
constexpr int FSMEM_BYTES = (F_QP + 2 * F_K + 2 * F_V) * 4;   // 106496

__global__ __launch_bounds__(256) void flash_kernel(
    const float* __restrict__ q, const float* __restrict__ k,
    const float* __restrict__ v, float* __restrict__ ctx, int Sk) {
    extern __shared__ float fsm[];
    uint32_t smem0 = (uint32_t)__cvta_generic_to_shared(fsm);

    int tid = threadIdx.x, lane = tid & 31, warp = tid >> 5;
    int q0 = blockIdx.x * FQ;
    int bh = blockIdx.y, b = bh / H, h = bh % H;
    const float* Qg = q + ((size_t)(b * L) + q0) * D + h * DH;
    const float* Kg = k + (size_t)b * Sk * D + h * DH;
    const float* Vg = v + (size_t)b * Sk * D + h * DH;

    int rbase = tid >> 4, c4 = (tid & 15) * 4;

    #pragma unroll
    for (int i = 0; i < 8; ++i) {
        int r = i * 16 + rbase;
        cpasync16(smem0 + (uint32_t)(r * QSTR + c4) * 4u, Qg + (size_t)r * D + c4);
    }
    auto ldK = [&](int it, int buf) {
        const float* src = Kg + (size_t)it * FKV * D;
        uint32_t base = smem0 + (uint32_t)(F_QP + buf * F_K) * 4u;
        #pragma unroll
        for (int i = 0; i < 4; ++i) {
            int r = i * 16 + rbase;
            cpasync16(base + (uint32_t)(r * QSTR + c4) * 4u, src + (size_t)r * D + c4);
        }
    };
    auto ldV = [&](int it, int buf) {
        const float* src = Vg + (size_t)it * FKV * D;
        uint32_t base = smem0 + (uint32_t)(F_QP + 2 * F_K + buf * F_V) * 4u;
        #pragma unroll
        for (int i = 0; i < 4; ++i) {
            int r = i * 16 + rbase;
            cpasync16(base + (uint32_t)(r * VSTR + c4) * 4u, src + (size_t)r * D + c4);
        }
    };
    ldK(0, 0); ldV(0, 0);
    cp_commit();
    cp_wait0();
    __syncthreads();

    int c = lane & 3, rq = lane >> 2;
    int prow = warp * 16 + rq;

    uint32_t qf[8][4];
    {
        const uint32_t* Qu = (const uint32_t*)fsm;
        #pragma unroll
        for (int kk = 0; kk < 8; ++kk) {
            qf[kk][0] = __float_as_uint(0.125f * __uint_as_float(Qu[prow * QSTR + kk * 8 + c]));
            qf[kk][1] = __float_as_uint(0.125f * __uint_as_float(Qu[(prow + 8) * QSTR + kk * 8 + c]));
            qf[kk][2] = __float_as_uint(0.125f * __uint_as_float(Qu[prow * QSTR + kk * 8 + c + 4]));
            qf[kk][3] = __float_as_uint(0.125f * __uint_as_float(Qu[(prow + 8) * QSTR + kk * 8 + c + 4]));
        }
    }
    __syncthreads();

    float of[8][4];
    #pragma unroll
    for (int nt = 0; nt < 8; ++nt)
        #pragma unroll
        for (int i = 0; i < 4; ++i) of[nt][i] = 0.f;
    float m0 = -3.0e38f, m1 = -3.0e38f, l0 = 0.f, l1 = 0.f;

    int nIter = Sk / FKV;
    for (int it = 0; it < nIter; ++it) {
        int cur = it & 1, nxt = cur ^ 1;
        if (it + 1 < nIter) { ldK(it + 1, nxt); ldV(it + 1, nxt); }
        cp_commit();

        const uint32_t* Ks = (const uint32_t*)fsm + F_QP + cur * F_K;
        const uint32_t* Vs = (const uint32_t*)fsm + F_QP + 2 * F_K + cur * F_V;

        float sf[8][4];
        #pragma unroll
        for (int nt = 0; nt < 8; ++nt)
            #pragma unroll
            for (int i = 0; i < 4; ++i) sf[nt][i] = 0.f;
        #pragma unroll
        for (int kk = 0; kk < 8; ++kk) {
            #pragma unroll
            for (int nt = 0; nt < 8; ++nt) {
                uint32_t b0 = Ks[(nt * 8 + rq) * QSTR + kk * 8 + c];
                uint32_t b1 = Ks[(nt * 8 + rq) * QSTR + kk * 8 + c + 4];
                mma_tf32(sf[nt][0], sf[nt][1], sf[nt][2], sf[nt][3],
                         qf[kk][0], qf[kk][1], qf[kk][2], qf[kk][3], b0, b1);
            }
        }

        float mx0 = -3.0e38f, mx1 = -3.0e38f;
        #pragma unroll
        for (int nt = 0; nt < 8; ++nt) {
            mx0 = fmaxf(mx0, fmaxf(sf[nt][0], sf[nt][1]));
            mx1 = fmaxf(mx1, fmaxf(sf[nt][2], sf[nt][3]));
        }
        mx0 = fmaxf(mx0, __shfl_xor_sync(0xffffffffu, mx0, 1));
        mx0 = fmaxf(mx0, __shfl_xor_sync(0xffffffffu, mx0, 2));
        mx1 = fmaxf(mx1, __shfl_xor_sync(0xffffffffu, mx1, 1));
        mx1 = fmaxf(mx1, __shfl_xor_sync(0xffffffffu, mx1, 2));
        float mn0 = fmaxf(m0, mx0), mn1 = fmaxf(m1, mx1);
        float f0 = __expf(m0 - mn0), f1 = __expf(m1 - mn1);

        float* Ps = fsm;
        float rs0 = 0.f, rs1 = 0.f;
        #pragma unroll
        for (int nt = 0; nt < 8; ++nt) {
            float p0 = __expf(sf[nt][0] - mn0);
            float p1 = __expf(sf[nt][1] - mn0);
            float p2 = __expf(sf[nt][2] - mn1);
            float p3 = __expf(sf[nt][3] - mn1);
            rs0 += p0 + p1; rs1 += p2 + p3;
            *(float2*)&Ps[prow * QSTR + nt * 8 + 2 * c] = make_float2(p0, p1);
            *(float2*)&Ps[(prow + 8) * QSTR + nt * 8 + 2 * c] = make_float2(p2, p3);
        }
        rs0 += __shfl_xor_sync(0xffffffffu, rs0, 1);
        rs0 += __shfl_xor_sync(0xffffffffu, rs0, 2);
        rs1 += __shfl_xor_sync(0xffffffffu, rs1, 1);
        rs1 += __shfl_xor_sync(0xffffffffu, rs1, 2);
        l0 = l0 * f0 + rs0; l1 = l1 * f1 + rs1;
        m0 = mn0; m1 = mn1;
        #pragma unroll
        for (int nt = 0; nt < 8; ++nt) {
            of[nt][0] *= f0; of[nt][1] *= f0;
            of[nt][2] *= f1; of[nt][3] *= f1;
        }
        __syncwarp();

        const uint32_t* Pu = (const uint32_t*)fsm;
        #pragma unroll
        for (int kk = 0; kk < 8; ++kk) {
            uint32_t a0 = Pu[prow * QSTR + kk * 8 + c];
            uint32_t a1 = Pu[(prow + 8) * QSTR + kk * 8 + c];
            uint32_t a2 = Pu[prow * QSTR + kk * 8 + c + 4];
            uint32_t a3 = Pu[(prow + 8) * QSTR + kk * 8 + c + 4];
            #pragma unroll
            for (int nt = 0; nt < 8; ++nt) {
                uint32_t b0 = Vs[(kk * 8 + c) * VSTR + nt * 8 + rq];
                uint32_t b1 = Vs[(kk * 8 + c + 4) * VSTR + nt * 8 + rq];
                mma_tf32(of[nt][0], of[nt][1], of[nt][2], of[nt][3],
                         a0, a1, a2, a3, b0, b1);
            }
        }
        cp_wait0();
        __syncthreads();
    }

    float il0 = 1.f / l0, il1 = 1.f / l1;
    int rg = b * L + q0 + warp * 16 + rq;
    float* dst0 = ctx + (size_t)rg * D + h * DH;
    float* dst1 = ctx + (size_t)(rg + 8) * D + h * DH;
    #pragma unroll
    for (int nt = 0; nt < 8; ++nt) {
        *(float2*)(dst0 + nt * 8 + 2 * c) = make_float2(of[nt][0] * il0, of[nt][1] * il0);
        *(float2*)(dst1 + nt * 8 + 2 * c) = make_float2(of[nt][2] * il1, of[nt][3] * il1);
    }
}

// ---------------------------------------------------------------------------
// Dict row L2-normalize: writes fp32 (for exact rescore) + bf16 (for GEMM)
// ---------------------------------------------------------------------------
__global__ __launch_bounds__(256) void rownorm_dual_kernel(
    const float* __restrict__ x, float* __restrict__ y,
    __nv_bfloat16* __restrict__ yb) {
    __shared__ float sh[256];
    size_t row = blockIdx.x;
    int tid = threadIdx.x;
    const float* xr = x + row * D;
    float* yr = y + row * D;
    __nv_bfloat16* ybr = yb + row * D;
    float v0 = xr[tid], v1 = xr[tid + 256], v2 = xr[tid + 512];
    float ss = blockReduceSum(v0 * v0 + v1 * v1 + v2 * v2, sh);
    float inv = rsqrtf(ss);
    float o0 = v0 * inv, o1 = v1 * inv, o2 = v2 * inv;
    yr[tid] = o0; yr[tid + 256] = o1; yr[tid + 512] = o2;
    ybr[tid] = __float2bfloat16(o0);
    ybr[tid + 256] = __float2bfloat16(o1);
    ybr[tid + 512] = __float2bfloat16(o2);
}

// ---------------------------------------------------------------------------
// fp32 -> bf16 convert (local feats, query side of sim GEMM)
// ---------------------------------------------------------------------------
__global__ __launch_bounds__(256) void tobf16_kernel(
    const float* __restrict__ x, __nv_bfloat16* __restrict__ y) {
    size_t base = (size_t)blockIdx.x * D;
    int tid = threadIdx.x;
    #pragma unroll
    for (int i = 0; i < 3; ++i) {
        int j = tid + (i << 8);
        y[base + j] = __float2bfloat16(x[base + j]);
    }
}

// ---------------------------------------------------------------------------
// Transpose + convert: Wt[n,k] = bf16(W[k,n]).  W is [D,D] fp32.
// grid (24, 24), block (32, 8).
// ---------------------------------------------------------------------------
__global__ void transpose_bf16_kernel(
    const float* __restrict__ W, __nv_bfloat16* __restrict__ Wt) {
    __shared__ float t[32][33];
    int bx = blockIdx.x * 32;   // n tile
    int by = blockIdx.y * 32;   // k tile
    int x = threadIdx.x, y = threadIdx.y;
    #pragma unroll
    for (int i = 0; i < 32; i += 8)
        t[y + i][x] = W[(size_t)(by + y + i) * D + bx + x];   // t[k_local][n_local]
    __syncthreads();
    #pragma unroll
    for (int i = 0; i < 32; i += 8)
        Wt[(size_t)(bx + y + i) * D + by + x] = __float2bfloat16(t[x][y + i]);
}

// ---------------------------------------------------------------------------
// Gather retrieved prototypes as bf16 (gfeats only feeds bf16 K/V GEMMs)
// ---------------------------------------------------------------------------
__global__ __launch_bounds__(256) void gather_bf16_kernel(
    const float* __restrict__ dict, const int* __restrict__ topk,
    __nv_bfloat16* __restrict__ gfeats) {
    int r = blockIdx.x;
    int b = r >> 11;
    int pos = r & 2047;
    int idx = topk[((size_t)(b * L + (pos >> 3))) * KP + (pos & 7)];
    const float* src = dict + (size_t)idx * D;
    __nv_bfloat16* dst = gfeats + (size_t)r * D;
    for (int j = threadIdx.x; j < D / 4; j += 256) {
        float4 v = ((const float4*)src)[j];
        __nv_bfloat162 lo = __floats2bfloat162_rn(v.x, v.y);
        __nv_bfloat162 hi = __floats2bfloat162_rn(v.z, v.w);
        ((__nv_bfloat162*)dst)[j * 2] = lo;
        ((__nv_bfloat162*)dst)[j * 2 + 1] = hi;
    }
}

// ---------------------------------------------------------------------------
// Fused tail: ll = LN(proj+local), lg = LN(proj2+local), o = LN(ll+lg),
// gate = sigmoid(o.aug_w + aug_b + local.ori_w + ori_b),
// out = gate*o + (1-gate)*local
// ---------------------------------------------------------------------------
__global__ __launch_bounds__(256) void tail_kernel(
    const float* __restrict__ proj, const float* __restrict__ proj2,
    const float* __restrict__ local,
    const float* __restrict__ g0, const float* __restrict__ b0,
    const float* __restrict__ g1, const float* __restrict__ b1,
    const float* __restrict__ g2, const float* __restrict__ b2,
    const float* __restrict__ aug_w, const float* __restrict__ aug_b,
    const float* __restrict__ ori_w, const float* __restrict__ ori_b,
    float* __restrict__ out) {
    __shared__ float sh[256];
    size_t base = (size_t)blockIdx.x * D;
    int tid = threadIdx.x;
    float a[3], bb[3], lf[3];
    #pragma unroll
    for (int t = 0; t < 3; ++t) {
        int i = tid + (t << 8);
        lf[t] = local[base + i];
        a[t] = proj[base + i] + lf[t];
        bb[t] = proj2[base + i] + lf[t];
    }
    float mean = blockReduceSum(a[0] + a[1] + a[2], sh) * (1.0f / 768.0f);
    float d0 = a[0] - mean, d1 = a[1] - mean, d2 = a[2] - mean;
    float var = blockReduceSum(d0 * d0 + d1 * d1 + d2 * d2, sh) * (1.0f / 768.0f);
    float inv = rsqrtf(var + 1e-12f);
    float llv[3];
    #pragma unroll
    for (int t = 0; t < 3; ++t) {
        int i = tid + (t << 8);
        llv[t] = (a[t] - mean) * inv * g0[i] + b0[i];
    }
    mean = blockReduceSum(bb[0] + bb[1] + bb[2], sh) * (1.0f / 768.0f);
    d0 = bb[0] - mean; d1 = bb[1] - mean; d2 = bb[2] - mean;
    var = blockReduceSum(d0 * d0 + d1 * d1 + d2 * d2, sh) * (1.0f / 768.0f);
    inv = rsqrtf(var + 1e-12f);
    float s[3];
    #pragma unroll
    for (int t = 0; t < 3; ++t) {
        int i = tid + (t << 8);
        s[t] = llv[t] + (bb[t] - mean) * inv * g1[i] + b1[i];
    }
    mean = blockReduceSum(s[0] + s[1] + s[2], sh) * (1.0f / 768.0f);
    d0 = s[0] - mean; d1 = s[1] - mean; d2 = s[2] - mean;
    var = blockReduceSum(d0 * d0 + d1 * d1 + d2 * d2, sh) * (1.0f / 768.0f);
    inv = rsqrtf(var + 1e-12f);
    float o[3];
    float dsum = 0.f;
    #pragma unroll
    for (int t = 0; t < 3; ++t) {
        int i = tid + (t << 8);
        o[t] = (s[t] - mean) * inv * g2[i] + b2[i];
        dsum += o[t] * aug_w[i] + lf[t] * ori_w[i];
    }
    dsum = blockReduceSum(dsum, sh);
    float gate = 1.0f / (1.0f + expf(-(dsum + aug_b[0] + ori_b[0])));
    #pragma unroll
    for (int t = 0; t < 3; ++t) {
        int i = tid + (t << 8);
        out[base + i] = gate * o[t] + (1.0f - gate) * lf[t];
    }
}

// ---------------------------------------------------------------------------
// Host launcher
// ---------------------------------------------------------------------------
extern "C" void kernel_launch(void* const* d_in, const int* in_sizes, int n_in,
                              void* d_out, int out_size) {
    (void)n_in; (void)out_size;
    const float* local = (const float*)d_in[0];
    const float* dict  = (const float*)d_in[1];

    bool sig = (in_sizes[3] == 768);
    const float *W[2][4], *Bi[2][4], *LNG[2], *LNB[2];
    for (int p = 0; p < 2; ++p) {
        int base = 2 + p * 10;
        if (sig) {
            for (int j = 0; j < 4; ++j) {
                W[p][j]  = (const float*)d_in[base + 2 * j];
                Bi[p][j] = (const float*)d_in[base + 2 * j + 1];
            }
        } else {
            for (int j = 0; j < 4; ++j) {
                W[p][j]  = (const float*)d_in[base + j];
                Bi[p][j] = (const float*)d_in[base + 4 + j];
            }
        }
        LNG[p] = (const float*)d_in[base + 8];
        LNB[p] = (const float*)d_in[base + 9];
    }
    const float* ln_g = (const float*)d_in[22];
    const float* ln_b = (const float*)d_in[23];
    const float *aug_w, *aug_b, *ori_w, *ori_b;
    if (in_sizes[25] == 1) {
        aug_w = (const float*)d_in[24]; aug_b = (const float*)d_in[25];
        ori_w = (const float*)d_in[26]; ori_b = (const float*)d_in[27];
    } else {
        aug_w = (const float*)d_in[24]; ori_w = (const float*)d_in[25];
        aug_b = (const float*)d_in[26]; ori_b = (const float*)d_in[27];
    }

    float *p_gnorm, *p_sim, *p_q, *p_q2, *p_k, *p_v;
    float *p_ctx, *p_ctx2, *p_proj, *p_proj2;
    __nv_bfloat16 *p_gnorm_bf, *p_local_bf, *p_gfeats_bf, *p_wkt, *p_wvt;
    int *p_cand, *p_topk;
    cudaGetSymbolAddress((void**)&p_gnorm, g_gnorm);
    cudaGetSymbolAddress((void**)&p_gnorm_bf, g_gnorm_bf);
    cudaGetSymbolAddress((void**)&p_local_bf, g_local_bf);
    cudaGetSymbolAddress((void**)&p_sim, g_sim);
    cudaGetSymbolAddress((void**)&p_cand, g_cand);
    cudaGetSymbolAddress((void**)&p_topk, g_topk);
    cudaGetSymbolAddress((void**)&p_gfeats_bf, g_gfeats_bf);
    cudaGetSymbolAddress((void**)&p_wkt, g_wkt);
    cudaGetSymbolAddress((void**)&p_wvt, g_wvt);
    cudaGetSymbolAddress((void**)&p_q, g_q);
    cudaGetSymbolAddress((void**)&p_q2, g_q2);
    cudaGetSymbolAddress((void**)&p_k, g_k);
    cudaGetSymbolAddress((void**)&p_v, g_v);
    cudaGetSymbolAddress((void**)&p_ctx, g_ctx);
    cudaGetSymbolAddress((void**)&p_ctx2, g_ctx2);
    cudaGetSymbolAddress((void**)&p_proj, g_proj);
    cudaGetSymbolAddress((void**)&p_proj2, g_proj2);

    const int SM_BF  = 2 * (2 * 128 * 20) * 4;          // 40960 (bf16 NT)
    const int SM_NN  = 2 * (128 * 36 + 32 * 136) * 4;   // 71680

    cudaFuncSetAttribute(bf16gemm_nt<false>,
                         cudaFuncAttributeMaxDynamicSharedMemorySize, SM_BF);
    cudaFuncSetAttribute(bf16gemm_nt<true>,
                         cudaFuncAttributeMaxDynamicSharedMemorySize, SM_BF);
    cudaFuncSetAttribute(tf32gemm_nn_multi,
                         cudaFuncAttributeMaxDynamicSharedMemorySize, SM_NN);
    cudaFuncSetAttribute(flash_kernel,
                         cudaFuncAttributeMaxDynamicSharedMemorySize, FSMEM_BYTES);

    // 1) normalize dict rows (fp32 + bf16); convert local; transpose K/V weights
    rownorm_dual_kernel<<<NDICT, 256>>>(dict, p_gnorm, p_gnorm_bf);
    tobf16_kernel<<<M, 256>>>(local, p_local_bf);
    transpose_bf16_kernel<<<dim3(24, 24), dim3(32, 8)>>>(W[1][1], p_wkt);
    transpose_bf16_kernel<<<dim3(24, 24), dim3(32, 8)>>>(W[1][2], p_wvt);

    // 2) approx sim = local_bf @ gnorm_bf^T (bf16 MMA, fp32 accum)
    bf16gemm_nt<false><<<dim3(NDICT / 128, M / 128), 256, SM_BF>>>(
        p_local_bf, p_gnorm_bf, nullptr, p_sim, D, D, D, NDICT);

    // 3) top-16 candidates -> exact fp32 rescore -> top-8 -> gather (bf16)
    topk16_kernel<<<M, 256>>>(p_sim, p_cand);
    rescore_kernel<<<M, 256>>>(local, p_gnorm, p_cand, p_topk);
    gather_bf16_kernel<<<B * SKG, 256>>>(dict, p_topk, p_gfeats_bf);

    // 4) merged small projections: ll Q,K,V + lg Q (tf32; all read `local`)
    {
        Ptrs4 p;
        p.A[0] = local;    p.A[1] = local;    p.A[2] = local;    p.A[3] = local;
        p.W[0] = W[0][0];  p.W[1] = W[0][1];  p.W[2] = W[0][2];  p.W[3] = W[1][0];
        p.bias[0] = Bi[0][0]; p.bias[1] = Bi[0][1]; p.bias[2] = Bi[0][2]; p.bias[3] = Bi[1][0];
        p.C[0] = p_q;      p.C[1] = p_k;      p.C[2] = p_v;      p.C[3] = p_q2;
        tf32gemm_nn_multi<<<dim3(24, M / 128), 256, SM_NN>>>(p);
    }

    // 5) ll fused attention
    flash_kernel<<<dim3(L / FQ, BH), 256, FSMEM_BYTES>>>(p_q, p_k, p_v, p_ctx, L);

    // 6) lg K,V projections over gathered prototypes (bf16 NT vs transposed W)
    bf16gemm_nt<true><<<dim3(D / 128, (B * SKG) / 128), 256, SM_BF>>>(
        p_gfeats_bf, p_wkt, Bi[1][1], p_k, D, D, D, D);
    bf16gemm_nt<true><<<dim3(D / 128, (B * SKG) / 128), 256, SM_BF>>>(
        p_gfeats_bf, p_wvt, Bi[1][2], p_v, D, D, D, D);

    // 7) lg fused attention
    flash_kernel<<<dim3(L / FQ, BH), 256, FSMEM_BYTES>>>(p_q2, p_k, p_v, p_ctx2, SKG);

    // 8) merged output projections (tf32)
    {
        Ptrs4 p;
        p.A[0] = p_ctx;    p.A[1] = p_ctx2;   p.A[2] = p_ctx;    p.A[3] = p_ctx2;
        p.W[0] = W[0][3];  p.W[1] = W[1][3];  p.W[2] = W[0][3];  p.W[3] = W[1][3];
        p.bias[0] = Bi[0][3]; p.bias[1] = Bi[1][3]; p.bias[2] = Bi[0][3]; p.bias[3] = Bi[1][3];
        p.C[0] = p_proj;   p.C[1] = p_proj2;  p.C[2] = p_proj;   p.C[3] = p_proj2;
        tf32gemm_nn_multi<<<dim3(12, M / 128), 256, SM_NN>>>(p);
    }

    // 9) fused tail: both residual LNs + final LN + gating
    tail_kernel<<<M, 256>>>(p_proj, p_proj2, local,
                            LNG[0], LNB[0], LNG[1], LNB[1], ln_g, ln_b,
                            aug_w, aug_b, ori_w, ori_b, (float*)d_out);
}